// round 1
// baseline (speedup 1.0000x reference)
#include <cuda_runtime.h>
#include <cuda_bf16.h>
#include <cstdint>

// Problem constants
#define B_   8
#define C_   256
#define T_   1600
#define H_   8
#define D_   32
#define BH_  64
#define M_   (B_*T_)   // 12800 token rows

// Scratch (device globals: allocation-free per harness rules)
__device__ __nv_bfloat16 g_tokens[M_ * C_];      // LN output, (B*T, C) bf16
__device__ __nv_bfloat16 g_Q[BH_ * T_ * D_];     // (B*H, T, 32) bf16
__device__ __nv_bfloat16 g_K[BH_ * T_ * D_];     // (B*H, T, 32) bf16

__device__ __forceinline__ float ex2f_(float x){
    float y; asm("ex2.approx.ftz.f32 %0, %1;" : "=f"(y) : "f"(x)); return y;
}

#define MMA_BF16(c0,c1,c2,c3,a0,a1,a2,a3,b0,b1)                          \
    asm volatile("mma.sync.aligned.m16n8k16.row.col.f32.bf16.bf16.f32 "  \
        "{%0,%1,%2,%3}, {%4,%5,%6,%7}, {%8,%9}, {%0,%1,%2,%3};"          \
        : "+f"(c0), "+f"(c1), "+f"(c2), "+f"(c3)                         \
        : "r"(a0), "r"(a1), "r"(a2), "r"(a3), "r"(b0), "r"(b1))

// ---------------------------------------------------------------------------
// Kernel 1: LayerNorm + transpose (B,C,T) -> tokens (B*T, C) bf16
// grid (T/32, B), block 256. smem transpose tile 256c x 32t.
// ---------------------------------------------------------------------------
__global__ void ln_kernel(const float* __restrict__ feat,
                          const float* __restrict__ lw,
                          const float* __restrict__ lb)
{
    __shared__ float tile[32][257];   // [t][c], padded: conflict-free both ways
    int b  = blockIdx.y;
    int t0 = blockIdx.x * 32;
    int tid = threadIdx.x;

    // Load: 32 consecutive threads read 32 consecutive t for one c (coalesced)
    #pragma unroll
    for (int i = 0; i < 32; i++){
        int idx = tid + i * 256;
        int c = idx >> 5, t = idx & 31;
        tile[t][c] = feat[(size_t)(b * C_ + c) * T_ + t0 + t];
    }
    __syncthreads();

    int wid = tid >> 5, lane = tid & 31;
    #pragma unroll
    for (int k = 0; k < 4; k++){
        int t = wid * 4 + k;
        float v[8]; float s = 0.f, s2 = 0.f;
        #pragma unroll
        for (int j = 0; j < 8; j++){
            v[j] = tile[t][lane + 32*j];
            s += v[j]; s2 += v[j]*v[j];
        }
        #pragma unroll
        for (int o = 16; o; o >>= 1){
            s  += __shfl_xor_sync(~0u, s,  o);
            s2 += __shfl_xor_sync(~0u, s2, o);
        }
        float mu  = s  * (1.f/256.f);
        float var = s2 * (1.f/256.f) - mu*mu;
        float rs  = rsqrtf(var + 1e-6f);
        size_t row = (size_t)(b * T_ + t0 + t) * C_;
        #pragma unroll
        for (int j = 0; j < 8; j++){
            int c = lane + 32*j;
            float o_ = (v[j] - mu) * rs * lw[c] + lb[c];
            g_tokens[row + c] = __float2bfloat16_rn(o_);
        }
    }
}

// ---------------------------------------------------------------------------
// Kernel 2: QKV projection (q,k only: N=512), bf16 mma, fp32 accum.
// out[m,j] = sum_c tokens[m,c] * W[j,c] + bias[j]
// grid (M/128, 512/64), block 256 (8 warps: 4m x 2n, warp tile 32x32)
// ---------------------------------------------------------------------------
__device__ __forceinline__ void storeQK(int m, int j, float v0, float v1){
    int b = m / T_;
    int t = m - b * T_;
    __nv_bfloat16* base; int jj;
    if (j < 256){ base = g_Q; jj = j; } else { base = g_K; jj = j - 256; }
    int hh = jj >> 5, d = jj & 31;   // j even -> d even, pair stays in-head
    *(__nv_bfloat162*)(base + (size_t)((b * H_ + hh) * T_ + t) * D_ + d) =
        __floats2bfloat162_rn(v0, v1);
}

__global__ void qkv_kernel(const float* __restrict__ W,
                           const float* __restrict__ bias)
{
    __shared__ __nv_bfloat16 As[128][24];  // [m][k], +8 pad -> conflict-free frags
    __shared__ __nv_bfloat16 Bs[64][24];   // [n][k]
    int tid  = threadIdx.x;
    int warp = tid >> 5, lane = tid & 31;
    int g = lane >> 2, tq = lane & 3;
    int warpM = warp >> 1, warpN = warp & 1;
    int m0 = blockIdx.x * 128, n0 = blockIdx.y * 64;

    int ar = tid >> 1, ah = tid & 1;   // A loader: row ar, 8 bf16 at k=ah*8
    int br = tid >> 2, bq = tid & 3;   // B loader: row br, 4 fp32 at k=bq*4

    float c[2][4][4];
    #pragma unroll
    for (int mt=0; mt<2; mt++)
        #pragma unroll
        for (int nt=0; nt<4; nt++)
            c[mt][nt][0]=c[mt][nt][1]=c[mt][nt][2]=c[mt][nt][3]=0.f;

    uint4  aReg = *(const uint4*)(g_tokens + (size_t)(m0+ar)*C_ + ah*8);
    float4 bReg = *(const float4*)(W + (size_t)(n0+br)*C_ + bq*4);

    #pragma unroll 1
    for (int kt = 0; kt < 16; kt++){
        *(uint4*)&As[ar][ah*8] = aReg;
        __nv_bfloat162 w01 = __floats2bfloat162_rn(bReg.x, bReg.y);
        __nv_bfloat162 w23 = __floats2bfloat162_rn(bReg.z, bReg.w);
        *(__nv_bfloat162*)&Bs[br][bq*4]     = w01;
        *(__nv_bfloat162*)&Bs[br][bq*4 + 2] = w23;
        __syncthreads();
        if (kt < 15){
            int k0 = (kt+1) * 16;
            aReg = *(const uint4*)(g_tokens + (size_t)(m0+ar)*C_ + k0 + ah*8);
            bReg = *(const float4*)(W + (size_t)(n0+br)*C_ + k0 + bq*4);
        }
        #pragma unroll
        for (int mt = 0; mt < 2; mt++){
            int am = warpM*32 + mt*16;
            unsigned a0 = *(const unsigned*)&As[am+g  ][2*tq];
            unsigned a1 = *(const unsigned*)&As[am+g+8][2*tq];
            unsigned a2 = *(const unsigned*)&As[am+g  ][2*tq+8];
            unsigned a3 = *(const unsigned*)&As[am+g+8][2*tq+8];
            #pragma unroll
            for (int nt = 0; nt < 4; nt++){
                int bn = warpN*32 + nt*8 + g;
                unsigned b0 = *(const unsigned*)&Bs[bn][2*tq];
                unsigned b1 = *(const unsigned*)&Bs[bn][2*tq+8];
                MMA_BF16(c[mt][nt][0],c[mt][nt][1],c[mt][nt][2],c[mt][nt][3],
                         a0,a1,a2,a3,b0,b1);
            }
        }
        __syncthreads();
    }
    #pragma unroll
    for (int mt=0; mt<2; mt++){
        #pragma unroll
        for (int nt=0; nt<4; nt++){
            int j = n0 + warpN*32 + nt*8 + 2*tq;
            float bi0 = bias[j], bi1 = bias[j+1];
            int m = m0 + warpM*32 + mt*16 + g;
            storeQK(m,   j, c[mt][nt][0]+bi0, c[mt][nt][1]+bi1);
            storeQK(m+8, j, c[mt][nt][2]+bi0, c[mt][nt][3]+bi1);
        }
    }
}

// ---------------------------------------------------------------------------
// Kernel 3: attention scores + softmax, two-pass recompute (no 655MB staging).
// grid (T/64, B*H), block 128 (4 warps, each warp = 16 q-rows).
// K streamed in 64-row double-buffered smem tiles. Max-subtraction skipped
// (scores ~N(0,0.1^2); exp range trivially safe in fp32).
// ---------------------------------------------------------------------------
__global__ void attn_kernel(float* __restrict__ out)
{
    __shared__ __nv_bfloat16 Qs[64][40];       // +8 pad
    __shared__ __nv_bfloat16 Ks[2][64][40];
    int tid  = threadIdx.x;
    int warp = tid >> 5, lane = tid & 31;
    int g = lane >> 2, tq = lane & 3;
    int m0 = blockIdx.x * 64;
    int bh = blockIdx.y;
    int r = tid >> 1, hs = tid & 1;            // tile loader: row r, half hs

    const __nv_bfloat16* Qbase = g_Q + (size_t)bh * T_ * D_;
    const __nv_bfloat16* Kbase = g_K + (size_t)bh * T_ * D_;

    {   // load Q tile (64x32)
        const uint4* s = (const uint4*)(Qbase + (size_t)(m0 + r) * D_ + hs*16);
        uint4 q0 = s[0], q1 = s[1];
        *(uint4*)&Qs[r][hs*16]     = q0;
        *(uint4*)&Qs[r][hs*16 + 8] = q1;
    }
    uint4 p0, p1;
    {   // prologue: K tile 0
        const uint4* s = (const uint4*)(Kbase + (size_t)r * D_ + hs*16);
        p0 = s[0]; p1 = s[1];
    }
    *(uint4*)&Ks[0][r][hs*16]     = p0;
    *(uint4*)&Ks[0][r][hs*16 + 8] = p1;
    __syncthreads();

    // Hoist Q fragments (warp's 16 rows) into registers for both passes
    unsigned a[2][4];
    int w16 = warp * 16;
    #pragma unroll
    for (int kk = 0; kk < 2; kk++){
        a[kk][0] = *(const unsigned*)&Qs[w16+g  ][kk*16 + 2*tq];
        a[kk][1] = *(const unsigned*)&Qs[w16+g+8][kk*16 + 2*tq];
        a[kk][2] = *(const unsigned*)&Qs[w16+g  ][kk*16 + 2*tq + 8];
        a[kk][3] = *(const unsigned*)&Qs[w16+g+8][kk*16 + 2*tq + 8];
    }

    const float SC = 0.17677669529663687f * 1.4426950408889634f; // scale*log2e

    // ---- PASS 1: row sums of exp(score) ----
    float sum0 = 0.f, sum8 = 0.f;
    #pragma unroll 1
    for (int it = 0; it < 25; it++){
        int buf = it & 1;
        if (it < 24){
            const uint4* s = (const uint4*)(Kbase + (size_t)((it+1)*64 + r) * D_ + hs*16);
            p0 = s[0]; p1 = s[1];
        }
        float c[8][4];
        #pragma unroll
        for (int nt=0;nt<8;nt++){ c[nt][0]=c[nt][1]=c[nt][2]=c[nt][3]=0.f; }
        #pragma unroll
        for (int kk=0;kk<2;kk++){
            #pragma unroll
            for (int nt=0;nt<8;nt++){
                unsigned b0 = *(const unsigned*)&Ks[buf][nt*8+g][kk*16 + 2*tq];
                unsigned b1 = *(const unsigned*)&Ks[buf][nt*8+g][kk*16 + 2*tq + 8];
                MMA_BF16(c[nt][0],c[nt][1],c[nt][2],c[nt][3],
                         a[kk][0],a[kk][1],a[kk][2],a[kk][3], b0, b1);
            }
        }
        #pragma unroll
        for (int nt=0;nt<8;nt++){
            sum0 += ex2f_(c[nt][0]*SC) + ex2f_(c[nt][1]*SC);
            sum8 += ex2f_(c[nt][2]*SC) + ex2f_(c[nt][3]*SC);
        }
        if (it < 24){
            *(uint4*)&Ks[buf^1][r][hs*16]     = p0;
            *(uint4*)&Ks[buf^1][r][hs*16 + 8] = p1;
        }
        __syncthreads();
    }
    sum0 += __shfl_xor_sync(~0u, sum0, 1); sum0 += __shfl_xor_sync(~0u, sum0, 2);
    sum8 += __shfl_xor_sync(~0u, sum8, 1); sum8 += __shfl_xor_sync(~0u, sum8, 2);
    float rinv0 = 1.f / sum0, rinv8 = 1.f / sum8;

    // ---- PASS 2: recompute scores, write normalized probabilities ----
    {
        const uint4* s = (const uint4*)(Kbase + (size_t)r * D_ + hs*16);
        p0 = s[0]; p1 = s[1];
    }
    *(uint4*)&Ks[0][r][hs*16]     = p0;
    *(uint4*)&Ks[0][r][hs*16 + 8] = p1;
    __syncthreads();

    float* ob = out + (size_t)bh * T_ * T_;
    int row0 = m0 + w16 + g;
    #pragma unroll 1
    for (int it = 0; it < 25; it++){
        int buf = it & 1;
        if (it < 24){
            const uint4* s = (const uint4*)(Kbase + (size_t)((it+1)*64 + r) * D_ + hs*16);
            p0 = s[0]; p1 = s[1];
        }
        float c[8][4];
        #pragma unroll
        for (int nt=0;nt<8;nt++){ c[nt][0]=c[nt][1]=c[nt][2]=c[nt][3]=0.f; }
        #pragma unroll
        for (int kk=0;kk<2;kk++){
            #pragma unroll
            for (int nt=0;nt<8;nt++){
                unsigned b0 = *(const unsigned*)&Ks[buf][nt*8+g][kk*16 + 2*tq];
                unsigned b1 = *(const unsigned*)&Ks[buf][nt*8+g][kk*16 + 2*tq + 8];
                MMA_BF16(c[nt][0],c[nt][1],c[nt][2],c[nt][3],
                         a[kk][0],a[kk][1],a[kk][2],a[kk][3], b0, b1);
            }
        }
        #pragma unroll
        for (int nt=0;nt<8;nt++){
            int col = it*64 + nt*8 + 2*tq;
            float2 v0 = make_float2(ex2f_(c[nt][0]*SC)*rinv0, ex2f_(c[nt][1]*SC)*rinv0);
            float2 v1 = make_float2(ex2f_(c[nt][2]*SC)*rinv8, ex2f_(c[nt][3]*SC)*rinv8);
            *(float2*)(ob + (size_t)row0      * T_ + col) = v0;
            *(float2*)(ob + (size_t)(row0+8)  * T_ + col) = v1;
        }
        if (it < 24){
            *(uint4*)&Ks[buf^1][r][hs*16]     = p0;
            *(uint4*)&Ks[buf^1][r][hs*16 + 8] = p1;
        }
        __syncthreads();
    }
}

// ---------------------------------------------------------------------------
extern "C" void kernel_launch(void* const* d_in, const int* in_sizes, int n_in,
                              void* d_out, int out_size)
{
    (void)in_sizes; (void)n_in; (void)out_size;
    const float* feat = (const float*)d_in[0];
    const float* lw   = (const float*)d_in[1];
    const float* lb   = (const float*)d_in[2];
    const float* qw   = (const float*)d_in[3];
    const float* qb   = (const float*)d_in[4];
    float* out = (float*)d_out;

    ln_kernel  <<<dim3(T_/32, B_), 256>>>(feat, lw, lb);
    qkv_kernel <<<dim3(M_/128, 512/64), 256>>>(qw, qb);
    attn_kernel<<<dim3(T_/64, BH_), 128>>>(out);
}